// round 4
// baseline (speedup 1.0000x reference)
#include <cuda_runtime.h>

#define BB 256
#define TT 512
#define NT 128
#define GO_IDX 1
#define EOS_IDX 2
#define NEGV -10000.0f

// Scratch (allocation-free rule: __device__ globals)
__device__ float  g_alphas[BB * TT * NT];   // 64 MB alphas trajectory
__device__ float2 g_stats[BB * TT];         // per-(b,t) {rowmax, log(sum exp(u-rowmax))}
__device__ int    g_len[BB];                // normalized int32 lengths

// ---------------------------------------------------------------------------
// Kernel 0: normalize lengths dtype (int32 vs int64) + defensive clamp.
// True lengths are in [T/2, T] (always > 0). If the buffer is int64, the
// int32 view is [lo0, 0, lo1, 0, ...] -> probe lens32[1]==0 distinguishes.
// Both probes are within the minimum possible buffer size (256 * 4B).
// ---------------------------------------------------------------------------
__global__ void lens_kernel(const int* __restrict__ lens32) {
    int b = threadIdx.x;                     // 256 threads, 1 block
    bool is64 = (lens32[1] == 0);
    int v = is64 ? lens32[2 * b] : lens32[b];
    g_len[b] = min(max(v, 1), TT);
}

// ---------------------------------------------------------------------------
// Kernel A: per-row logsumexp stats (bandwidth bound, ~67MB read)
// ---------------------------------------------------------------------------
__global__ void stats_kernel(const float* __restrict__ u) {
    int warp = blockIdx.x * (blockDim.x >> 5) + (threadIdx.x >> 5);
    int lane = threadIdx.x & 31;
    if (warp >= BB * TT) return;
    const float4* row = reinterpret_cast<const float4*>(u + (size_t)warp * NT);
    float4 v = row[lane];
    float m = fmaxf(fmaxf(v.x, v.y), fmaxf(v.z, v.w));
    #pragma unroll
    for (int o = 16; o; o >>= 1) m = fmaxf(m, __shfl_xor_sync(0xffffffffu, m, o));
    float s = expf(v.x - m) + expf(v.y - m) + expf(v.z - m) + expf(v.w - m);
    #pragma unroll
    for (int o = 16; o; o >>= 1) s += __shfl_xor_sync(0xffffffffu, s, o);
    if (lane == 0) g_stats[warp] = make_float2(m, logf(s));
}

// ---------------------------------------------------------------------------
// Kernel B: forward Viterbi recurrence. 1 block per batch, 1 thread per tag.
// trans row in registers; alphas in double-buffered smem (broadcast LDS.128).
// No argmax tracking (recomputed in backtrace). Early exit at lengths[b].
// ---------------------------------------------------------------------------
__global__ __launch_bounds__(128) void forward_kernel(
    const float* __restrict__ u,
    const float* __restrict__ trans)
{
    int b = blockIdx.x;
    int cur = threadIdx.x;

    // cache this tag's transition row in registers (128 regs)
    float rt[NT];
    #pragma unroll
    for (int p = 0; p < NT; p++) rt[p] = __ldg(trans + cur * NT + p);

    __shared__ __align__(16) float abuf[2][NT];
    abuf[0][cur] = (cur == GO_IDX) ? 0.0f : NEGV;   // exact log_softmax of init

    int len = g_len[b];
    const float*  ub = u + (size_t)b * TT * NT;
    const float2* st = g_stats + (size_t)b * TT;
    float*        ao = g_alphas + (size_t)b * TT * NT;
    __syncthreads();

    for (int t = 0; t < len; t++) {
        float  uv = ub[t * NT + cur];   // issued early; consumed after the loop
        float2 s  = st[t];
        const float4* a4 = reinterpret_cast<const float4*>(abuf[t & 1]);
        float m0 = -3.4e38f, m1 = -3.4e38f, m2 = -3.4e38f, m3 = -3.4e38f;
        #pragma unroll
        for (int q = 0; q < NT / 4; q++) {
            float4 a = a4[q];
            m0 = fmaxf(m0, a.x + rt[4 * q + 0]);
            m1 = fmaxf(m1, a.y + rt[4 * q + 1]);
            m2 = fmaxf(m2, a.z + rt[4 * q + 2]);
            m3 = fmaxf(m3, a.w + rt[4 * q + 3]);
        }
        float m = fmaxf(fmaxf(m0, m1), fmaxf(m2, m3));
        // probv = (u - rowmax) - L  (matches reference's log_softmax form;
        // any ULP error in L is uniform across tags -> decisions invariant)
        float na = m + ((uv - s.x) - s.y);
        abuf[(t + 1) & 1][cur] = na;
        ao[t * NT + cur] = na;
        __syncthreads();
    }
}

// ---------------------------------------------------------------------------
// Kernel C: terminal argmax + backtrace (recompute backpointers). Warp/batch.
// ---------------------------------------------------------------------------
__device__ __forceinline__ unsigned fmono(float f) {
    unsigned u = __float_as_uint(f);
    return (u & 0x80000000u) ? ~u : (u | 0x80000000u);
}
__device__ __forceinline__ float fmono_inv(unsigned m) {
    return (m & 0x80000000u) ? __uint_as_float(m & 0x7fffffffu)
                             : __uint_as_float(~m);
}

__global__ void backtrace_kernel(
    const float* __restrict__ trans,
    float* __restrict__ out)
{
    int b = blockIdx.x;
    int lane = threadIdx.x;        // 32 threads
    int len = g_len[b];
    float* preds = out + (size_t)b * TT;

    // preds[t] = 0 for t >= len
    for (int t = len + lane; t < TT; t += 32) preds[t] = 0.0f;

    const float* ab = g_alphas + (size_t)b * TT * NT;

    // terminal: argmax_cur( alphas[len-1][cur] + trans[EOS][cur] ), first-max ties
    float4 a  = reinterpret_cast<const float4*>(ab + (size_t)(len - 1) * NT)[lane];
    float4 tv = reinterpret_cast<const float4*>(trans + EOS_IDX * NT)[lane];
    unsigned c0 = fmono(a.x + tv.x), c1 = fmono(a.y + tv.y);
    unsigned c2 = fmono(a.z + tv.z), c3 = fmono(a.w + tv.w);
    unsigned best = max(max(c0, c1), max(c2, c3));
    unsigned wmax = __reduce_max_sync(0xffffffffu, best);
    unsigned idx = 0x7fffffffu;
    if (c3 == wmax) idx = 4u * lane + 3u;
    if (c2 == wmax) idx = 4u * lane + 2u;
    if (c1 == wmax) idx = 4u * lane + 1u;
    if (c0 == wmax) idx = 4u * lane + 0u;
    int tag = (int)__reduce_min_sync(0xffffffffu, idx);
    if (lane == 0) {
        out[(size_t)BB * TT + b] = fmono_inv(wmax);  // path score (exact max)
        preds[len - 1] = (float)tag;
    }

    // backtrace with alphas prefetch one step ahead
    float4 av_pf;
    if (len >= 2)
        av_pf = reinterpret_cast<const float4*>(ab + (size_t)(len - 2) * NT)[lane];
    for (int t = len - 1; t >= 1; t--) {
        float4 av = av_pf;
        if (t > 1)
            av_pf = reinterpret_cast<const float4*>(ab + (size_t)(t - 2) * NT)[lane];
        float4 tr = reinterpret_cast<const float4*>(trans + tag * NT)[lane];
        c0 = fmono(av.x + tr.x); c1 = fmono(av.y + tr.y);
        c2 = fmono(av.z + tr.z); c3 = fmono(av.w + tr.w);
        best = max(max(c0, c1), max(c2, c3));
        wmax = __reduce_max_sync(0xffffffffu, best);
        idx = 0x7fffffffu;
        if (c3 == wmax) idx = 4u * lane + 3u;
        if (c2 == wmax) idx = 4u * lane + 2u;
        if (c1 == wmax) idx = 4u * lane + 1u;
        if (c0 == wmax) idx = 4u * lane + 0u;
        tag = (int)__reduce_min_sync(0xffffffffu, idx);
        if (lane == 0) preds[t - 1] = (float)tag;
    }
}

// ---------------------------------------------------------------------------
extern "C" void kernel_launch(void* const* d_in, const int* in_sizes, int n_in,
                              void* d_out, int out_size)
{
    const float* u     = (const float*)d_in[0];   // unaries [B,T,N] f32
    const float* trans = (const float*)d_in[1];   // trans  [1,N,N] f32
    const int*   lens  = (const int*)d_in[2];     // lengths [B] (i32 or i64, detected)
    float* out = (float*)d_out;                   // [B*T preds | B scores]

    lens_kernel<<<1, BB>>>(lens);
    stats_kernel<<<(BB * TT) / 8, 256>>>(u);
    forward_kernel<<<BB, 128>>>(u, trans);
    backtrace_kernel<<<BB, 32>>>(trans, out);
}